// round 3
// baseline (speedup 1.0000x reference)
#include <cuda_runtime.h>
#include <float.h>

#define B_N   8192
#define D_N   768
#define L_N   12288
#define TK1   32
#define TK2   128

// ---------------- scratch (device globals: allocation-free rule) ----------------
__device__ float g_pre[(size_t)B_N * L_N];      // 402 MB
__device__ float g_skip[(size_t)B_N * D_N];     // 25 MB
__device__ float g_topv[B_N * TK2];
__device__ int   g_topi[B_N * TK2];
__device__ float g_rowp[B_N * 4];               // per-row {s1, s2, sum_dec, sum_enc}
__device__ float g_colsum[32 * D_N];
__device__ float g_colsq[32 * D_N];

// ---------------- tiled fp32 GEMM: C[m,n] = sum_k A[m,k]*B'[..] + bias[n] ------
// TRANSB=true : B is [N,K] row-major (NT gemm, used for pre = x @ W_enc^T)
// TRANSB=false: B is [K,N] row-major (NN gemm, used for skip = x @ W_skip)
template<bool TRANSB>
__global__ __launch_bounds__(256)
void gemm_tiled(const float* __restrict__ A, const float* __restrict__ Bm,
                const float* __restrict__ bias, float* __restrict__ C,
                int M, int N, int K)
{
    const int BK = 16;
    __shared__ float As[16][128];
    __shared__ float Bs[16][128];

    int tid = threadIdx.x;
    int m0 = blockIdx.y * 128;
    int n0 = blockIdx.x * 128;
    int ty = tid >> 4;          // 0..15
    int tx = tid & 15;          // 0..15

    float acc[8][8];
#pragma unroll
    for (int i = 0; i < 8; i++)
#pragma unroll
        for (int j = 0; j < 8; j++) acc[i][j] = 0.f;

    for (int k0 = 0; k0 < K; k0 += BK) {
        // A tile: 128 rows x 16 k, transposed into As[k][m]
#pragma unroll
        for (int it = 0; it < 2; it++) {
            int s   = tid + it * 256;      // 512 float4 slots
            int row = s >> 2;              // 0..127
            int kq  = (s & 3) << 2;        // 0,4,8,12
            float4 v = *reinterpret_cast<const float4*>(&A[(size_t)(m0 + row) * K + k0 + kq]);
            As[kq + 0][row] = v.x; As[kq + 1][row] = v.y;
            As[kq + 2][row] = v.z; As[kq + 3][row] = v.w;
        }
        if (TRANSB) {
#pragma unroll
            for (int it = 0; it < 2; it++) {
                int s   = tid + it * 256;
                int row = s >> 2;
                int kq  = (s & 3) << 2;
                float4 v = *reinterpret_cast<const float4*>(&Bm[(size_t)(n0 + row) * K + k0 + kq]);
                Bs[kq + 0][row] = v.x; Bs[kq + 1][row] = v.y;
                Bs[kq + 2][row] = v.z; Bs[kq + 3][row] = v.w;
            }
        } else {
#pragma unroll
            for (int it = 0; it < 2; it++) {
                int s  = tid + it * 256;
                int kk = s >> 5;             // 0..15
                int nq = (s & 31) << 2;      // 0..124
                float4 v = *reinterpret_cast<const float4*>(&Bm[(size_t)(k0 + kk) * N + n0 + nq]);
                *reinterpret_cast<float4*>(&Bs[kk][nq]) = v;
            }
        }
        __syncthreads();

#pragma unroll
        for (int kk = 0; kk < BK; kk++) {
            float ra[8], rb[8];
#pragma unroll
            for (int i = 0; i < 8; i++) ra[i] = As[kk][ty * 8 + i];
#pragma unroll
            for (int j = 0; j < 8; j++) rb[j] = Bs[kk][tx * 8 + j];
#pragma unroll
            for (int i = 0; i < 8; i++)
#pragma unroll
                for (int j = 0; j < 8; j++)
                    acc[i][j] = fmaf(ra[i], rb[j], acc[i][j]);
        }
        __syncthreads();
    }

#pragma unroll
    for (int i = 0; i < 8; i++) {
        float* cp = &C[(size_t)(m0 + ty * 8 + i) * N + n0 + tx * 8];
#pragma unroll
        for (int j = 0; j < 8; j += 4) {
            float4 v;
            v.x = acc[i][j + 0] + bias[n0 + tx * 8 + j + 0];
            v.y = acc[i][j + 1] + bias[n0 + tx * 8 + j + 1];
            v.z = acc[i][j + 2] + bias[n0 + tx * 8 + j + 2];
            v.w = acc[i][j + 3] + bias[n0 + tx * 8 + j + 3];
            *reinterpret_cast<float4*>(&cp[j]) = v;
        }
    }
}

// ---------------- bitonic sort (descending by value, tie: smaller index first) --
__device__ __forceinline__ bool pair_greater(float va, int ia, float vb, int ib)
{
    return (va > vb) || (va == vb && ia < ib);
}

__device__ void bitonic_desc(float* v, int* id, int n, int tid)
{
    for (int k = 2; k <= n; k <<= 1) {
        for (int j = k >> 1; j > 0; j >>= 1) {
            for (int i = tid; i < n; i += 256) {
                int ixj = i ^ j;
                if (ixj > i) {
                    bool desc = ((i & k) == 0);
                    bool sw = desc ? pair_greater(v[ixj], id[ixj], v[i], id[i])
                                   : pair_greater(v[i], id[i], v[ixj], id[ixj]);
                    if (sw) {
                        float tv = v[i]; v[i] = v[ixj]; v[ixj] = tv;
                        int   ti = id[i]; id[i] = id[ixj]; id[ixj] = ti;
                    }
                }
            }
            __syncthreads();
        }
    }
}

// ---------------- per-row top-128 via 12-bit radix histogram --------------------
__global__ __launch_bounds__(256)
void topk_kernel(void)
{
    __shared__ unsigned hist[4096];
    __shared__ unsigned chunksum[256];
    __shared__ float candv[1024];
    __shared__ int   candi[1024];
    __shared__ float selv[TK2];
    __shared__ int   seli[TK2];
    __shared__ int   sh_bstar, sh_cgt;
    __shared__ unsigned n_sure, n_cand;

    int row = blockIdx.x;
    int tid = threadIdx.x;
    const float* p = g_pre + (size_t)row * L_N;

    for (int i = tid; i < 4096; i += 256) hist[i] = 0;
    if (tid == 0) { n_sure = 0; n_cand = 0; }
    __syncthreads();

    for (int c = tid; c < L_N; c += 256) {
        unsigned u = __float_as_uint(p[c]);
        unsigned key = (u & 0x80000000u) ? ~u : (u | 0x80000000u);
        atomicAdd(&hist[key >> 20], 1u);
    }
    __syncthreads();

    {
        unsigned s = 0;
#pragma unroll
        for (int b = 0; b < 16; b++) s += hist[tid * 16 + b];
        chunksum[tid] = s;
    }
    __syncthreads();

    if (tid == 0) {
        unsigned acc = 0; int bstar = 0; unsigned cgt = 0;
        for (int ch = 255; ch >= 0; ch--) {
            if (acc + chunksum[ch] >= (unsigned)TK2) {
                for (int b = ch * 16 + 15; b >= ch * 16; b--) {
                    if (acc + hist[b] >= (unsigned)TK2) { bstar = b; cgt = acc; goto found; }
                    acc += hist[b];
                }
            }
            acc += chunksum[ch];
        }
found:
        sh_bstar = bstar; sh_cgt = (int)cgt;
    }
    __syncthreads();

    int bstar = sh_bstar;
    for (int c = tid; c < L_N; c += 256) {
        float v = p[c];
        unsigned u = __float_as_uint(v);
        unsigned key = (u & 0x80000000u) ? ~u : (u | 0x80000000u);
        int bin = (int)(key >> 20);
        if (bin > bstar) {
            unsigned pos = atomicAdd(&n_sure, 1u);
            selv[pos] = v; seli[pos] = c;
        } else if (bin == bstar) {
            unsigned pos = atomicAdd(&n_cand, 1u);
            if (pos < 1024) { candv[pos] = v; candi[pos] = c; }
        }
    }
    __syncthreads();

    int m = min((int)n_cand, 1024);
    int npow = 2; while (npow < m) npow <<= 1;
    for (int i = m + tid; i < npow; i += 256) { candv[i] = -FLT_MAX; candi[i] = 0x7fffffff; }
    __syncthreads();

    bitonic_desc(candv, candi, npow, tid);

    int cgt = sh_cgt;
    int r = TK2 - cgt;                 // 1..128 entries taken from the boundary bin
    for (int i = tid; i < r; i += 256) { selv[cgt + i] = candv[i]; seli[cgt + i] = candi[i]; }
    __syncthreads();

    bitonic_desc(selv, seli, TK2, tid);

    if (tid < TK2) {
        g_topv[row * TK2 + tid] = selv[tid];
        g_topi[row * TK2 + tid] = seli[tid];
    }
}

// ---------------- column stats of x for total_variance --------------------------
__global__ __launch_bounds__(256)
void colstats_kernel(const float* __restrict__ x)
{
    int col = blockIdx.x * 256 + threadIdx.x;   // gridDim.x = 3
    int rc  = blockIdx.y;                       // 32 row chunks of 256
    float s = 0.f, q = 0.f;
    for (int rr = 0; rr < 256; rr++) {
        float v = x[(size_t)(rc * 256 + rr) * D_N + col];
        s += v; q = fmaf(v, v, q);
    }
    g_colsum[rc * D_N + col] = s;
    g_colsq [rc * D_N + col] = q;
}

// ---------------- block-reduce helpers ------------------------------------------
__device__ __forceinline__ float block_reduce_f(float v, float* red, int tid)
{
    red[tid] = v; __syncthreads();
#pragma unroll
    for (int off = 128; off > 0; off >>= 1) {
        if (tid < off) red[tid] += red[tid + off];
        __syncthreads();
    }
    float r = red[0]; __syncthreads();
    return r;
}

__device__ __forceinline__ double block_reduce_d(double v, double* red, int tid)
{
    red[tid] = v; __syncthreads();
#pragma unroll
    for (int off = 128; off > 0; off >>= 1) {
        if (tid < off) red[tid] += red[tid + off];
        __syncthreads();
    }
    double r = red[0]; __syncthreads();
    return r;
}

// ---------------- fused sparse decode + per-row reductions ----------------------
// For each row b: p1 = sum_{j<32} relu(v)*Wdec[idx], p2 = sum_{j<128} ...
//   s1 = ||(MLP-skip) - p1||^2 ; s2 = ||(MLP-skip) - p2||^2
//   sum_dec = sum_d (2*skip + p1 + p2) ; sum_enc = sum relu(v)*(2 if j<32 else 1)
__global__ __launch_bounds__(256)
void decode_kernel(const float* __restrict__ mlp, const float* __restrict__ Wdec)
{
    __shared__ float sv[TK2];
    __shared__ int   si[TK2];
    __shared__ float red[256];

    int row = blockIdx.x;
    int tid = threadIdx.x;

    if (tid < TK2) {
        float v = g_topv[row * TK2 + tid];
        sv[tid] = v > 0.f ? v : 0.f;
        si[tid] = g_topi[row * TK2 + tid];
    }
    __syncthreads();

    int c0 = tid, c1 = tid + 256, c2 = tid + 512;
    size_t base = (size_t)row * D_N;
    float sk0 = g_skip[base + c0], sk1 = g_skip[base + c1], sk2 = g_skip[base + c2];
    float R0 = mlp[base + c0] - sk0;
    float R1 = mlp[base + c1] - sk1;
    float R2 = mlp[base + c2] - sk2;

    float p0 = 0.f, p1 = 0.f, p2 = 0.f;
    float q0 = 0.f, q1 = 0.f, q2 = 0.f;
#pragma unroll 4
    for (int j = 0; j < TK2; j++) {
        float v = sv[j];
        const float* w = Wdec + (size_t)si[j] * D_N;
        p0 = fmaf(v, w[c0], p0);
        p1 = fmaf(v, w[c1], p1);
        p2 = fmaf(v, w[c2], p2);
        if (j == TK1 - 1) { q0 = p0; q1 = p1; q2 = p2; }
    }

    float e0 = R0 - q0, e1 = R1 - q1, e2 = R2 - q2;
    float s1v = e0 * e0 + e1 * e1 + e2 * e2;
    e0 = R0 - p0; e1 = R1 - p1; e2 = R2 - p2;
    float s2v = e0 * e0 + e1 * e1 + e2 * e2;
    float dsum = 2.f * (sk0 + sk1 + sk2) + q0 + q1 + q2 + p0 + p1 + p2;
    float ev = (tid < TK2) ? sv[tid] * ((tid < TK1) ? 2.f : 1.f) : 0.f;

    float r0 = block_reduce_f(s1v,  red, tid);
    float r1 = block_reduce_f(s2v,  red, tid);
    float r2 = block_reduce_f(dsum, red, tid);
    float r3 = block_reduce_f(ev,   red, tid);
    if (tid == 0) {
        g_rowp[row * 4 + 0] = r0;
        g_rowp[row * 4 + 1] = r1;
        g_rowp[row * 4 + 2] = r2;
        g_rowp[row * 4 + 3] = r3;
    }
}

// ---------------- final deterministic reduction ---------------------------------
__global__ __launch_bounds__(256)
void final_kernel(float* __restrict__ out)
{
    __shared__ double dred[256];
    int tid = threadIdx.x;

    double tv = 0.0;
    for (int col = tid; col < D_N; col += 256) {
        double S = 0.0, Q = 0.0;
        for (int i = 0; i < 32; i++) {
            S += (double)g_colsum[i * D_N + col];
            Q += (double)g_colsq [i * D_N + col];
        }
        tv += Q - S * S / (double)B_N;
    }

    double S1 = 0.0, S2 = 0.0, SD = 0.0, SE = 0.0;
    for (int r = tid; r < B_N; r += 256) {
        S1 += (double)g_rowp[r * 4 + 0];
        S2 += (double)g_rowp[r * 4 + 1];
        SD += (double)g_rowp[r * 4 + 2];
        SE += (double)g_rowp[r * 4 + 3];
    }

    tv = block_reduce_d(tv, dred, tid);
    S1 = block_reduce_d(S1, dred, tid);
    S2 = block_reduce_d(S2, dred, tid);
    SD = block_reduce_d(SD, dred, tid);
    SE = block_reduce_d(SE, dred, tid);

    if (tid == 0) {
        out[0] = (float)(SE / ((double)B_N * (double)L_N));
        out[1] = (float)(SD / ((double)B_N * (double)D_N));
        out[2] = (float)(S1 / tv + (S2 / tv) / 8.0);
    }
}

// ---------------- launch --------------------------------------------------------
extern "C" void kernel_launch(void* const* d_in, const int* in_sizes, int n_in,
                              void* d_out, int out_size)
{
    const float* x     = (const float*)d_in[0];
    const float* mlp   = (const float*)d_in[1];
    const float* Wenc  = (const float*)d_in[2];
    const float* benc  = (const float*)d_in[3];
    const float* Wdec  = (const float*)d_in[4];
    const float* bdec  = (const float*)d_in[5];
    const float* Wskip = (const float*)d_in[6];
    float* out = (float*)d_out;

    float* pre_ptr  = nullptr;
    float* skip_ptr = nullptr;
    cudaGetSymbolAddress((void**)&pre_ptr,  g_pre);
    cudaGetSymbolAddress((void**)&skip_ptr, g_skip);

    // skip = x @ W_skip + b_dec   (NN)
    gemm_tiled<false><<<dim3(D_N / 128, B_N / 128), 256>>>(x, Wskip, bdec, skip_ptr,
                                                           B_N, D_N, D_N);
    // pre = x @ W_enc^T + b_enc   (NT)
    gemm_tiled<true><<<dim3(L_N / 128, B_N / 128), 256>>>(x, Wenc, benc, pre_ptr,
                                                          B_N, L_N, D_N);
    // per-row top-128 (sorted desc; top-32 is the prefix)
    topk_kernel<<<B_N, 256>>>();
    // column stats for total_variance
    colstats_kernel<<<dim3(3, 32), 256>>>(x);
    // fused sparse decode + per-row loss/mean partials
    decode_kernel<<<B_N, 256>>>(mlp, Wdec);
    // final reduction to the 3 scalars
    final_kernel<<<1, 256>>>(out);
}

// round 5
// speedup vs baseline: 1.7388x; 1.7388x over previous
#include <cuda_runtime.h>
#include <cuda_bf16.h>
#include <float.h>
#include <stdint.h>

#define B_N   8192
#define D_N   768
#define L_N   12288
#define TK1   32
#define TK2   128
#define TKE   160          // selected (sorted) entries per row, with refinement margin
#define KSPL  2304         // 3 * D_N : bf16x3 split K

// GEMM tiling
#define BM 128
#define BN 128
#define BK 32              // bf16 elements per K chunk (64 bytes)
#define GSTG 3             // cp.async pipeline stages
#define NCHUNK (KSPL / BK) // 72
#define PADE 40            // smem row stride in elements (32 + 8 pad) = 80 bytes
#define TILE_BYTES (128 * PADE * 2)       // 10240 per operand per stage
#define GSM_TOTAL (GSTG * 2 * TILE_BYTES) // 61440

// ---------------- scratch (device globals: allocation-free rule) ----------------
__device__ float g_pre[(size_t)B_N * L_N];              // 402 MB
__device__ float g_skip[(size_t)B_N * D_N];             // 25 MB
__device__ __nv_bfloat16 g_xs[(size_t)B_N * KSPL];      // [xh | xh | xl]
__device__ __nv_bfloat16 g_we[(size_t)L_N * KSPL];      // [wh | wl | wh]
__device__ __nv_bfloat16 g_wsT[(size_t)D_N * KSPL];     // W_skip^T split
__device__ float g_topv[B_N * TK2];
__device__ int   g_topi[B_N * TK2];
__device__ float g_rowp[B_N * 4];
__device__ float g_colsum[32 * D_N];
__device__ float g_colsq[32 * D_N];

// ================= helpers ======================================================
__device__ __forceinline__ uint32_t smem_u32(const void* p) {
    uint32_t a;
    asm("{ .reg .u64 t; cvta.to.shared.u64 t, %1; cvt.u32.u64 %0, t; }" : "=r"(a) : "l"(p));
    return a;
}
__device__ __forceinline__ void cp16(uint32_t dst, const void* src) {
    asm volatile("cp.async.cg.shared.global [%0], [%1], 16;" :: "r"(dst), "l"(src));
}
#define CP_COMMIT() asm volatile("cp.async.commit_group;" ::: "memory")
#define CP_WAIT1()  asm volatile("cp.async.wait_group 1;" ::: "memory")

__device__ __forceinline__ void ldm_x4(uint32_t& r0, uint32_t& r1, uint32_t& r2,
                                       uint32_t& r3, uint32_t addr)
{
    asm volatile("ldmatrix.sync.aligned.m8n8.x4.shared.b16 {%0,%1,%2,%3}, [%4];"
                 : "=r"(r0), "=r"(r1), "=r"(r2), "=r"(r3) : "r"(addr));
}

__device__ __forceinline__ void mma16816(float* d, const uint32_t* a, const uint32_t* b)
{
    asm volatile(
        "mma.sync.aligned.m16n8k16.row.col.f32.bf16.bf16.f32 "
        "{%0,%1,%2,%3}, {%4,%5,%6,%7}, {%8,%9}, {%0,%1,%2,%3};"
        : "+f"(d[0]), "+f"(d[1]), "+f"(d[2]), "+f"(d[3])
        : "r"(a[0]), "r"(a[1]), "r"(a[2]), "r"(a[3]), "r"(b[0]), "r"(b[1]));
}

// ================= bf16x3 split conversion kernels ==============================
__global__ __launch_bounds__(256)
void split_x_kernel(const float* __restrict__ x)
{
    int i = blockIdx.x * 256 + threadIdx.x;          // over B_N*D_N
    int b = i / D_N, d = i - b * D_N;
    float v = x[i];
    __nv_bfloat16 h = __float2bfloat16(v);
    __nv_bfloat16 l = __float2bfloat16(v - __bfloat162float(h));
    size_t ro = (size_t)b * KSPL;
    g_xs[ro + d] = h; g_xs[ro + D_N + d] = h; g_xs[ro + 2 * D_N + d] = l;
}

__global__ __launch_bounds__(256)
void split_we_kernel(const float* __restrict__ w)
{
    int i = blockIdx.x * 256 + threadIdx.x;          // over L_N*D_N
    int n = i / D_N, d = i - n * D_N;
    float v = w[i];
    __nv_bfloat16 h = __float2bfloat16(v);
    __nv_bfloat16 l = __float2bfloat16(v - __bfloat162float(h));
    size_t ro = (size_t)n * KSPL;
    g_we[ro + d] = h; g_we[ro + D_N + d] = l; g_we[ro + 2 * D_N + d] = h;
}

__global__ __launch_bounds__(256)
void split_ws_kernel(const float* __restrict__ w)   // W_skip [D,D] -> transposed split
{
    int i = blockIdx.x * 256 + threadIdx.x;          // over D_N*D_N
    int n = i / D_N, d = i - n * D_N;
    float v = w[(size_t)d * D_N + n];
    __nv_bfloat16 h = __float2bfloat16(v);
    __nv_bfloat16 l = __float2bfloat16(v - __bfloat162float(h));
    size_t ro = (size_t)n * KSPL;
    g_wsT[ro + d] = h; g_wsT[ro + D_N + d] = l; g_wsT[ro + 2 * D_N + d] = h;
}

// ================= mma.sync bf16 GEMM: C = A[M,K] @ B[N,K]^T + bias ============
// A rows = batch (BM=128), B rows = output features (BN=128), K-major both.
__global__ __launch_bounds__(256)
void gemm_mma(const __nv_bfloat16* __restrict__ A, const __nv_bfloat16* __restrict__ Bm,
              const float* __restrict__ bias, float* __restrict__ C, int N_ld)
{
    extern __shared__ char smem[];
    uint32_t sb = smem_u32(smem);
    int tid = threadIdx.x;
    int wid = tid >> 5, lane = tid & 31;
    int warp_m = wid & 1;          // 2 groups of 64 rows
    int warp_n = wid >> 1;         // 4 groups of 32 cols
    int m0 = blockIdx.y * BM, n0 = blockIdx.x * BN;

    const char* Ab = (const char*)(A + (size_t)m0 * KSPL);
    const char* Bb = (const char*)(Bm + (size_t)n0 * KSPL);

    auto load_chunk = [&](int stage, int chunk) {
        int kb = chunk * (BK * 2);                   // byte offset along K
        uint32_t sA = sb + stage * TILE_BYTES;
        uint32_t sB = sb + GSTG * TILE_BYTES + stage * TILE_BYTES;
#pragma unroll
        for (int i = 0; i < 2; i++) {                // A: 128 rows x 64B = 512 cp16
            int s = tid + i * 256; int r = s >> 2, c = s & 3;
            cp16(sA + r * (PADE * 2) + c * 16, Ab + (size_t)r * (KSPL * 2) + kb + c * 16);
        }
#pragma unroll
        for (int i = 0; i < 2; i++) {                // B: 128 rows x 64B
            int s = tid + i * 256; int r = s >> 2, c = s & 3;
            cp16(sB + r * (PADE * 2) + c * 16, Bb + (size_t)r * (KSPL * 2) + kb + c * 16);
        }
    };

    float acc[4][4][4];
#pragma unroll
    for (int i = 0; i < 4; i++)
#pragma unroll
        for (int j = 0; j < 4; j++)
#pragma unroll
            for (int r = 0; r < 4; r++) acc[i][j][r] = 0.f;

    for (int p = 0; p < GSTG - 1; p++) { load_chunk(p, p); CP_COMMIT(); }

    for (int c = 0; c < NCHUNK; c++) {
        int st = c % GSTG;
        CP_WAIT1();
        __syncthreads();
        int nc = c + GSTG - 1;
        if (nc < NCHUNK) load_chunk(nc % GSTG, nc);
        CP_COMMIT();

        uint32_t sA = sb + st * TILE_BYTES;
        uint32_t sB = sb + GSTG * TILE_BYTES + st * TILE_BYTES;
#pragma unroll
        for (int k16 = 0; k16 < 2; k16++) {
            uint32_t a[4][4], b[4][2];
            int acol = k16 * 16 + (lane >> 4) * 8;
#pragma unroll
            for (int mt = 0; mt < 4; mt++) {
                int row = warp_m * 64 + mt * 16 + (lane & 15);
                ldm_x4(a[mt][0], a[mt][1], a[mt][2], a[mt][3],
                       sA + row * (PADE * 2) + acol * 2);
            }
            int bn = ((lane >> 4) & 1) * 8 + (lane & 7);
            int bk = k16 * 16 + ((lane >> 3) & 1) * 8;
#pragma unroll
            for (int h = 0; h < 2; h++) {
                int nrow = warp_n * 32 + h * 16 + bn;
                uint32_t r0, r1, r2, r3;
                ldm_x4(r0, r1, r2, r3, sB + nrow * (PADE * 2) + bk * 2);
                b[2 * h][0] = r0; b[2 * h][1] = r1;
                b[2 * h + 1][0] = r2; b[2 * h + 1][1] = r3;
            }
#pragma unroll
            for (int mt = 0; mt < 4; mt++)
#pragma unroll
                for (int nt = 0; nt < 4; nt++)
                    mma16816(acc[mt][nt], a[mt], b[nt]);
        }
        __syncthreads();
    }

    // epilogue: c fragment -> global (float2 stores), add bias
    int gm = m0 + warp_m * 64;
    int gn = n0 + warp_n * 32;
    int lr = lane >> 2, lc = (lane & 3) * 2;
#pragma unroll
    for (int mt = 0; mt < 4; mt++) {
#pragma unroll
        for (int nt = 0; nt < 4; nt++) {
            int cc = gn + nt * 8 + lc;
            float b0 = bias[cc], b1 = bias[cc + 1];
            size_t o0 = (size_t)(gm + mt * 16 + lr) * N_ld + cc;
            size_t o1 = (size_t)(gm + mt * 16 + lr + 8) * N_ld + cc;
            float2 v0 = make_float2(acc[mt][nt][0] + b0, acc[mt][nt][1] + b1);
            float2 v1 = make_float2(acc[mt][nt][2] + b0, acc[mt][nt][3] + b1);
            *reinterpret_cast<float2*>(&C[o0]) = v0;
            *reinterpret_cast<float2*>(&C[o1]) = v1;
        }
    }
}

// ---------------- bitonic sort (descending by value, tie: smaller index first) --
__device__ __forceinline__ bool pair_greater(float va, int ia, float vb, int ib)
{
    return (va > vb) || (va == vb && ia < ib);
}

__device__ void bitonic_desc(float* v, int* id, int n, int tid)
{
    for (int k = 2; k <= n; k <<= 1) {
        for (int j = k >> 1; j > 0; j >>= 1) {
            for (int i = tid; i < n; i += 256) {
                int ixj = i ^ j;
                if (ixj > i) {
                    bool desc = ((i & k) == 0);
                    bool sw = desc ? pair_greater(v[ixj], id[ixj], v[i], id[i])
                                   : pair_greater(v[i], id[i], v[ixj], id[ixj]);
                    if (sw) {
                        float tv = v[i]; v[i] = v[ixj]; v[ixj] = tv;
                        int   ti = id[i]; id[i] = id[ixj]; id[ixj] = ti;
                    }
                }
            }
            __syncthreads();
        }
    }
}

// ---------------- per-row top-160 (radix) + exact-fp32 boundary refinement ------
__global__ __launch_bounds__(256)
void topk_kernel(const float* __restrict__ x, const float* __restrict__ Wenc,
                 const float* __restrict__ benc)
{
    __shared__ unsigned hist[4096];
    __shared__ unsigned chunksum[256];
    __shared__ float candv[1024];
    __shared__ int   candi[1024];
    __shared__ float selv[256];
    __shared__ int   seli[256];
    __shared__ int   sh_bstar, sh_cgt;
    __shared__ unsigned n_sure, n_cand;
    __shared__ int   nflag;
    __shared__ int   flagidx[96];

    int row = blockIdx.x;
    int tid = threadIdx.x;
    int wid = tid >> 5, lid = tid & 31;
    const float* p = g_pre + (size_t)row * L_N;

    for (int i = tid; i < 4096; i += 256) hist[i] = 0;
    if (tid == 0) { n_sure = 0; n_cand = 0; nflag = 0; }
    __syncthreads();

    for (int c = tid; c < L_N; c += 256) {
        unsigned u = __float_as_uint(p[c]);
        unsigned key = (u & 0x80000000u) ? ~u : (u | 0x80000000u);
        atomicAdd(&hist[key >> 20], 1u);
    }
    __syncthreads();

    {
        unsigned s = 0;
#pragma unroll
        for (int b = 0; b < 16; b++) s += hist[tid * 16 + b];
        chunksum[tid] = s;
    }
    __syncthreads();

    if (tid == 0) {
        unsigned acc = 0; int bstar = 0; unsigned cgt = 0;
        for (int ch = 255; ch >= 0; ch--) {
            if (acc + chunksum[ch] >= (unsigned)TKE) {
                for (int b = ch * 16 + 15; b >= ch * 16; b--) {
                    if (acc + hist[b] >= (unsigned)TKE) { bstar = b; cgt = acc; goto found; }
                    acc += hist[b];
                }
            }
            acc += chunksum[ch];
        }
found:
        sh_bstar = bstar; sh_cgt = (int)cgt;
    }
    __syncthreads();

    int bstar = sh_bstar;
    for (int c = tid; c < L_N; c += 256) {
        float v = p[c];
        unsigned u = __float_as_uint(v);
        unsigned key = (u & 0x80000000u) ? ~u : (u | 0x80000000u);
        int bin = (int)(key >> 20);
        if (bin > bstar) {
            unsigned pos = atomicAdd(&n_sure, 1u);
            selv[pos] = v; seli[pos] = c;
        } else if (bin == bstar) {
            unsigned pos = atomicAdd(&n_cand, 1u);
            if (pos < 1024) { candv[pos] = v; candi[pos] = c; }
        }
    }
    __syncthreads();

    int m = min((int)n_cand, 1024);
    int npow = 2; while (npow < m) npow <<= 1;
    for (int i = m + tid; i < npow; i += 256) { candv[i] = -FLT_MAX; candi[i] = 0x7fffffff; }
    __syncthreads();

    bitonic_desc(candv, candi, npow, tid);

    int cgt = sh_cgt;
    int r = TKE - cgt;
    for (int i = tid; i < r; i += 256) { selv[cgt + i] = candv[i]; seli[cgt + i] = candi[i]; }
    for (int i = TKE + tid; i < 256; i += 256) { selv[i] = -FLT_MAX; seli[i] = 0x7fffffff; }
    __syncthreads();

    bitonic_desc(selv, seli, 256, tid);

    // ---- exact fp32 refinement near the k=32 / k=128 boundaries ----
    {
        float thr1 = selv[TK1 - 1];
        float thr2 = selv[TK2 - 1];
        const float DELTA = 1e-4f;
        if (tid < TKE) {
            float v = selv[tid];
            if (fabsf(v - thr1) < DELTA || fabsf(v - thr2) < DELTA) {
                int pos = atomicAdd(&nflag, 1);
                if (pos < 96) flagidx[pos] = tid;
            }
        }
        __syncthreads();
        int nf = min(nflag, 96);
        for (int f = wid; f < nf; f += 8) {
            int j = flagidx[f];
            int col = seli[j];
            const float* xr = x + (size_t)row * D_N;
            const float* wr = Wenc + (size_t)col * D_N;
            float acc = 0.f;
            for (int d = lid; d < D_N; d += 32) acc = fmaf(xr[d], wr[d], acc);
#pragma unroll
            for (int off = 16; off > 0; off >>= 1)
                acc += __shfl_xor_sync(0xffffffffu, acc, off);
            if (lid == 0) selv[j] = acc + benc[col];
        }
        __syncthreads();
        if (nf > 0) bitonic_desc(selv, seli, 256, tid);
    }

    if (tid < TK2) {
        g_topv[row * TK2 + tid] = selv[tid];
        g_topi[row * TK2 + tid] = seli[tid];
    }
}

// ---------------- column stats of x for total_variance --------------------------
__global__ __launch_bounds__(256)
void colstats_kernel(const float* __restrict__ x)
{
    int col = blockIdx.x * 256 + threadIdx.x;
    int rc  = blockIdx.y;
    float s = 0.f, q = 0.f;
    for (int rr = 0; rr < 256; rr++) {
        float v = x[(size_t)(rc * 256 + rr) * D_N + col];
        s += v; q = fmaf(v, v, q);
    }
    g_colsum[rc * D_N + col] = s;
    g_colsq [rc * D_N + col] = q;
}

// ---------------- block-reduce helpers ------------------------------------------
__device__ __forceinline__ float block_reduce_f(float v, float* red, int tid)
{
    red[tid] = v; __syncthreads();
#pragma unroll
    for (int off = 128; off > 0; off >>= 1) {
        if (tid < off) red[tid] += red[tid + off];
        __syncthreads();
    }
    float r = red[0]; __syncthreads();
    return r;
}

__device__ __forceinline__ double block_reduce_d(double v, double* red, int tid)
{
    red[tid] = v; __syncthreads();
#pragma unroll
    for (int off = 128; off > 0; off >>= 1) {
        if (tid < off) red[tid] += red[tid + off];
        __syncthreads();
    }
    double r = red[0]; __syncthreads();
    return r;
}

// ---------------- fused sparse decode + per-row reductions ----------------------
__global__ __launch_bounds__(256)
void decode_kernel(const float* __restrict__ mlp, const float* __restrict__ Wdec)
{
    __shared__ float sv[TK2];
    __shared__ int   si[TK2];
    __shared__ float red[256];

    int row = blockIdx.x;
    int tid = threadIdx.x;

    if (tid < TK2) {
        float v = g_topv[row * TK2 + tid];
        sv[tid] = v > 0.f ? v : 0.f;
        si[tid] = g_topi[row * TK2 + tid];
    }
    __syncthreads();

    int c0 = tid, c1 = tid + 256, c2 = tid + 512;
    size_t base = (size_t)row * D_N;
    float sk0 = g_skip[base + c0], sk1 = g_skip[base + c1], sk2 = g_skip[base + c2];
    float R0 = mlp[base + c0] - sk0;
    float R1 = mlp[base + c1] - sk1;
    float R2 = mlp[base + c2] - sk2;

    float p0 = 0.f, p1 = 0.f, p2 = 0.f;
    float q0 = 0.f, q1 = 0.f, q2 = 0.f;
#pragma unroll 4
    for (int j = 0; j < TK2; j++) {
        float v = sv[j];
        const float* w = Wdec + (size_t)si[j] * D_N;
        p0 = fmaf(v, w[c0], p0);
        p1 = fmaf(v, w[c1], p1);
        p2 = fmaf(v, w[c2], p2);
        if (j == TK1 - 1) { q0 = p0; q1 = p1; q2 = p2; }
    }

    float e0 = R0 - q0, e1 = R1 - q1, e2 = R2 - q2;
    float s1v = e0 * e0 + e1 * e1 + e2 * e2;
    e0 = R0 - p0; e1 = R1 - p1; e2 = R2 - p2;
    float s2v = e0 * e0 + e1 * e1 + e2 * e2;
    float dsum = 2.f * (sk0 + sk1 + sk2) + q0 + q1 + q2 + p0 + p1 + p2;
    float ev = (tid < TK2) ? sv[tid] * ((tid < TK1) ? 2.f : 1.f) : 0.f;

    float r0 = block_reduce_f(s1v,  red, tid);
    float r1 = block_reduce_f(s2v,  red, tid);
    float r2 = block_reduce_f(dsum, red, tid);
    float r3 = block_reduce_f(ev,   red, tid);
    if (tid == 0) {
        g_rowp[row * 4 + 0] = r0;
        g_rowp[row * 4 + 1] = r1;
        g_rowp[row * 4 + 2] = r2;
        g_rowp[row * 4 + 3] = r3;
    }
}

// ---------------- final deterministic reduction ---------------------------------
__global__ __launch_bounds__(256)
void final_kernel(float* __restrict__ out)
{
    __shared__ double dred[256];
    int tid = threadIdx.x;

    double tv = 0.0;
    for (int col = tid; col < D_N; col += 256) {
        double S = 0.0, Q = 0.0;
        for (int i = 0; i < 32; i++) {
            S += (double)g_colsum[i * D_N + col];
            Q += (double)g_colsq [i * D_N + col];
        }
        tv += Q - S * S / (double)B_N;
    }

    double S1 = 0.0, S2 = 0.0, SD = 0.0, SE = 0.0;
    for (int r = tid; r < B_N; r += 256) {
        S1 += (double)g_rowp[r * 4 + 0];
        S2 += (double)g_rowp[r * 4 + 1];
        SD += (double)g_rowp[r * 4 + 2];
        SE += (double)g_rowp[r * 4 + 3];
    }

    tv = block_reduce_d(tv, dred, tid);
    S1 = block_reduce_d(S1, dred, tid);
    S2 = block_reduce_d(S2, dred, tid);
    SD = block_reduce_d(SD, dred, tid);
    SE = block_reduce_d(SE, dred, tid);

    if (tid == 0) {
        out[0] = (float)(SE / ((double)B_N * (double)L_N));
        out[1] = (float)(SD / ((double)B_N * (double)D_N));
        out[2] = (float)(S1 / tv + (S2 / tv) / 8.0);
    }
}

// ---------------- launch --------------------------------------------------------
extern "C" void kernel_launch(void* const* d_in, const int* in_sizes, int n_in,
                              void* d_out, int out_size)
{
    const float* x     = (const float*)d_in[0];
    const float* mlp   = (const float*)d_in[1];
    const float* Wenc  = (const float*)d_in[2];
    const float* benc  = (const float*)d_in[3];
    const float* Wdec  = (const float*)d_in[4];
    const float* bdec  = (const float*)d_in[5];
    const float* Wskip = (const float*)d_in[6];
    float* out = (float*)d_out;

    float* pre_ptr  = nullptr;
    float* skip_ptr = nullptr;
    __nv_bfloat16 *xs_ptr = nullptr, *we_ptr = nullptr, *ws_ptr = nullptr;
    cudaGetSymbolAddress((void**)&pre_ptr,  g_pre);
    cudaGetSymbolAddress((void**)&skip_ptr, g_skip);
    cudaGetSymbolAddress((void**)&xs_ptr,   g_xs);
    cudaGetSymbolAddress((void**)&we_ptr,   g_we);
    cudaGetSymbolAddress((void**)&ws_ptr,   g_wsT);

    cudaFuncSetAttribute(gemm_mma, cudaFuncAttributeMaxDynamicSharedMemorySize,
                         (int)GSM_TOTAL);

    // bf16x3 splits
    split_x_kernel <<<(B_N * D_N) / 256, 256>>>(x);
    split_we_kernel<<<(L_N * D_N) / 256, 256>>>(Wenc);
    split_ws_kernel<<<(D_N * D_N) / 256, 256>>>(Wskip);

    // independent column stats for total_variance
    colstats_kernel<<<dim3(3, 32), 256>>>(x);

    // skip = x @ W_skip + b_dec   via bf16x3 mma.sync
    gemm_mma<<<dim3(D_N / BN, B_N / BM), 256, GSM_TOTAL>>>(xs_ptr, ws_ptr, bdec,
                                                           skip_ptr, D_N);
    // pre = x @ W_enc^T + b_enc   via bf16x3 mma.sync
    gemm_mma<<<dim3(L_N / BN, B_N / BM), 256, GSM_TOTAL>>>(xs_ptr, we_ptr, benc,
                                                           pre_ptr, L_N);
    // per-row top-160 + exact boundary refinement -> sorted top-128
    topk_kernel<<<B_N, 256>>>(x, Wenc, benc);

    // fused sparse decode + per-row loss/mean partials
    decode_kernel<<<B_N, 256>>>(mlp, Wdec);

    // final reduction to the 3 scalars
    final_kernel<<<1, 256>>>(out);
}

// round 6
// speedup vs baseline: 2.7437x; 1.5779x over previous
#include <cuda_runtime.h>
#include <cuda_bf16.h>
#include <float.h>
#include <stdint.h>

#define B_N   8192
#define D_N   768
#define L_N   12288
#define TK1   32
#define TK2   128
#define TKE   160          // approx-selected candidates per row (margin 32 past TK2)
#define KSPL  2304         // 3 * D_N : bf16x3 split K (skip path only)

// GEMM tiling
#define BM 128
#define BN 128
#define BK 32              // bf16 elements per K chunk (64 bytes)
#define GSTG 3             // cp.async pipeline stages
#define PADE 40            // smem row stride in elements (32 + 8 pad)
#define TILE_BYTES (128 * PADE * 2)
#define GSM_TOTAL (GSTG * 2 * TILE_BYTES)

// ---------------- scratch (device globals: allocation-free rule) ----------------
__device__ float g_pre[(size_t)B_N * L_N];              // approx scores, 402 MB
__device__ float g_skip[(size_t)B_N * D_N];
__device__ __nv_bfloat16 g_xs[(size_t)B_N * KSPL];      // [xh | xh | xl] (skip gemm)
__device__ __nv_bfloat16 g_xh[(size_t)B_N * D_N];       // xh only (pre gemm)
__device__ __nv_bfloat16 g_weh[(size_t)L_N * D_N];      // Wenc hi (pre gemm)
__device__ __nv_bfloat16 g_wsT[(size_t)D_N * KSPL];     // W_skip^T split
__device__ float g_topv[B_N * TK2];
__device__ int   g_topi[B_N * TK2];
__device__ float g_rowp[B_N * 4];
__device__ float g_colsum[32 * D_N];
__device__ float g_colsq[32 * D_N];

// ================= helpers ======================================================
__device__ __forceinline__ uint32_t smem_u32(const void* p) {
    uint32_t a;
    asm("{ .reg .u64 t; cvta.to.shared.u64 t, %1; cvt.u32.u64 %0, t; }" : "=r"(a) : "l"(p));
    return a;
}
__device__ __forceinline__ void cp16(uint32_t dst, const void* src) {
    asm volatile("cp.async.cg.shared.global [%0], [%1], 16;" :: "r"(dst), "l"(src));
}
#define CP_COMMIT() asm volatile("cp.async.commit_group;" ::: "memory")
#define CP_WAIT1()  asm volatile("cp.async.wait_group 1;" ::: "memory")

__device__ __forceinline__ void ldm_x4(uint32_t& r0, uint32_t& r1, uint32_t& r2,
                                       uint32_t& r3, uint32_t addr)
{
    asm volatile("ldmatrix.sync.aligned.m8n8.x4.shared.b16 {%0,%1,%2,%3}, [%4];"
                 : "=r"(r0), "=r"(r1), "=r"(r2), "=r"(r3) : "r"(addr));
}

__device__ __forceinline__ void mma16816(float* d, const uint32_t* a, const uint32_t* b)
{
    asm volatile(
        "mma.sync.aligned.m16n8k16.row.col.f32.bf16.bf16.f32 "
        "{%0,%1,%2,%3}, {%4,%5,%6,%7}, {%8,%9}, {%0,%1,%2,%3};"
        : "+f"(d[0]), "+f"(d[1]), "+f"(d[2]), "+f"(d[3])
        : "r"(a[0]), "r"(a[1]), "r"(a[2]), "r"(a[3]), "r"(b[0]), "r"(b[1]));
}

// ================= conversion kernels ===========================================
__global__ __launch_bounds__(256)
void split_x_kernel(const float* __restrict__ x)
{
    int i = blockIdx.x * 256 + threadIdx.x;          // over B_N*D_N
    int b = i / D_N, d = i - b * D_N;
    float v = x[i];
    __nv_bfloat16 h = __float2bfloat16(v);
    __nv_bfloat16 l = __float2bfloat16(v - __bfloat162float(h));
    size_t ro = (size_t)b * KSPL;
    g_xs[ro + d] = h; g_xs[ro + D_N + d] = h; g_xs[ro + 2 * D_N + d] = l;
    g_xh[i] = h;
}

__global__ __launch_bounds__(256)
void conv_we_kernel(const float* __restrict__ w)
{
    int i = blockIdx.x * 256 + threadIdx.x;          // over L_N*D_N
    g_weh[i] = __float2bfloat16(w[i]);
}

__global__ __launch_bounds__(256)
void split_ws_kernel(const float* __restrict__ w)   // W_skip [D,D] -> transposed split
{
    int i = blockIdx.x * 256 + threadIdx.x;          // over D_N*D_N
    int n = i / D_N, d = i - n * D_N;
    float v = w[(size_t)d * D_N + n];
    __nv_bfloat16 h = __float2bfloat16(v);
    __nv_bfloat16 l = __float2bfloat16(v - __bfloat162float(h));
    size_t ro = (size_t)n * KSPL;
    g_wsT[ro + d] = h; g_wsT[ro + D_N + d] = l; g_wsT[ro + 2 * D_N + d] = h;
}

// ================= mma.sync bf16 GEMM: C = A[M,K] @ B[N,K]^T + bias ============
__global__ __launch_bounds__(256)
void gemm_mma(const __nv_bfloat16* __restrict__ A, const __nv_bfloat16* __restrict__ Bm,
              const float* __restrict__ bias, float* __restrict__ C, int N_ld, int K)
{
    extern __shared__ char smem[];
    uint32_t sb = smem_u32(smem);
    int tid = threadIdx.x;
    int wid = tid >> 5, lane = tid & 31;
    int warp_m = wid & 1;          // 2 groups of 64 rows
    int warp_n = wid >> 1;         // 4 groups of 32 cols
    int m0 = blockIdx.y * BM, n0 = blockIdx.x * BN;
    int nchunk = K / BK;

    const char* Ab = (const char*)(A + (size_t)m0 * K);
    const char* Bb = (const char*)(Bm + (size_t)n0 * K);

    auto load_chunk = [&](int stage, int chunk) {
        int kb = chunk * (BK * 2);
        uint32_t sA = sb + stage * TILE_BYTES;
        uint32_t sB = sb + GSTG * TILE_BYTES + stage * TILE_BYTES;
#pragma unroll
        for (int i = 0; i < 2; i++) {
            int s = tid + i * 256; int r = s >> 2, c = s & 3;
            cp16(sA + r * (PADE * 2) + c * 16, Ab + (size_t)r * (K * 2) + kb + c * 16);
        }
#pragma unroll
        for (int i = 0; i < 2; i++) {
            int s = tid + i * 256; int r = s >> 2, c = s & 3;
            cp16(sB + r * (PADE * 2) + c * 16, Bb + (size_t)r * (K * 2) + kb + c * 16);
        }
    };

    float acc[4][4][4];
#pragma unroll
    for (int i = 0; i < 4; i++)
#pragma unroll
        for (int j = 0; j < 4; j++)
#pragma unroll
            for (int r = 0; r < 4; r++) acc[i][j][r] = 0.f;

    for (int p = 0; p < GSTG - 1; p++) { load_chunk(p, p); CP_COMMIT(); }

    for (int c = 0; c < nchunk; c++) {
        int st = c % GSTG;
        CP_WAIT1();
        __syncthreads();
        int nc = c + GSTG - 1;
        if (nc < nchunk) load_chunk(nc % GSTG, nc);
        CP_COMMIT();

        uint32_t sA = sb + st * TILE_BYTES;
        uint32_t sB = sb + GSTG * TILE_BYTES + st * TILE_BYTES;
#pragma unroll
        for (int k16 = 0; k16 < 2; k16++) {
            uint32_t a[4][4], b[4][2];
            int acol = k16 * 16 + (lane >> 4) * 8;
#pragma unroll
            for (int mt = 0; mt < 4; mt++) {
                int row = warp_m * 64 + mt * 16 + (lane & 15);
                ldm_x4(a[mt][0], a[mt][1], a[mt][2], a[mt][3],
                       sA + row * (PADE * 2) + acol * 2);
            }
            int bn = ((lane >> 4) & 1) * 8 + (lane & 7);
            int bk = k16 * 16 + ((lane >> 3) & 1) * 8;
#pragma unroll
            for (int h = 0; h < 2; h++) {
                int nrow = warp_n * 32 + h * 16 + bn;
                uint32_t r0, r1, r2, r3;
                ldm_x4(r0, r1, r2, r3, sB + nrow * (PADE * 2) + bk * 2);
                b[2 * h][0] = r0; b[2 * h][1] = r1;
                b[2 * h + 1][0] = r2; b[2 * h + 1][1] = r3;
            }
#pragma unroll
            for (int mt = 0; mt < 4; mt++)
#pragma unroll
                for (int nt = 0; nt < 4; nt++)
                    mma16816(acc[mt][nt], a[mt], b[nt]);
        }
        __syncthreads();
    }

    int gm = m0 + warp_m * 64;
    int gn = n0 + warp_n * 32;
    int lr = lane >> 2, lc = (lane & 3) * 2;
#pragma unroll
    for (int mt = 0; mt < 4; mt++) {
#pragma unroll
        for (int nt = 0; nt < 4; nt++) {
            int cc = gn + nt * 8 + lc;
            float b0 = bias[cc], b1 = bias[cc + 1];
            size_t o0 = (size_t)(gm + mt * 16 + lr) * N_ld + cc;
            size_t o1 = (size_t)(gm + mt * 16 + lr + 8) * N_ld + cc;
            float2 v0 = make_float2(acc[mt][nt][0] + b0, acc[mt][nt][1] + b1);
            float2 v1 = make_float2(acc[mt][nt][2] + b0, acc[mt][nt][3] + b1);
            *reinterpret_cast<float2*>(&C[o0]) = v0;
            *reinterpret_cast<float2*>(&C[o1]) = v1;
        }
    }
}

// ---------------- bitonic sort (descending by value, tie: smaller index first) --
__device__ __forceinline__ bool pair_greater(float va, int ia, float vb, int ib)
{
    return (va > vb) || (va == vb && ia < ib);
}

__device__ void bitonic_desc(float* v, int* id, int n, int tid)
{
    for (int k = 2; k <= n; k <<= 1) {
        for (int j = k >> 1; j > 0; j >>= 1) {
            for (int i = tid; i < n; i += 256) {
                int ixj = i ^ j;
                if (ixj > i) {
                    bool desc = ((i & k) == 0);
                    bool sw = desc ? pair_greater(v[ixj], id[ixj], v[i], id[i])
                                   : pair_greater(v[i], id[i], v[ixj], id[ixj]);
                    if (sw) {
                        float tv = v[i]; v[i] = v[ixj]; v[ixj] = tv;
                        int   ti = id[i]; id[i] = id[ixj]; id[ixj] = ti;
                    }
                }
            }
            __syncthreads();
        }
    }
}

// ---------------- per-row top-160 (approx radix) + full exact fp32 recompute ----
__global__ __launch_bounds__(256)
void topk_kernel(const float* __restrict__ x, const float* __restrict__ Wenc,
                 const float* __restrict__ benc)
{
    __shared__ unsigned hist[4096];
    __shared__ unsigned chunksum[256];
    __shared__ float candv[1024];
    __shared__ int   candi[1024];
    __shared__ float selv[256];
    __shared__ int   seli[256];
    __shared__ float xrow[D_N];
    __shared__ int   sh_bstar, sh_cgt;
    __shared__ unsigned n_sure, n_cand;

    int row = blockIdx.x;
    int tid = threadIdx.x;
    int wid = tid >> 5, lid = tid & 31;
    const float* p = g_pre + (size_t)row * L_N;

    for (int i = tid; i < 4096; i += 256) hist[i] = 0;
    for (int d = tid; d < D_N; d += 256) xrow[d] = x[(size_t)row * D_N + d];
    if (tid == 0) { n_sure = 0; n_cand = 0; }
    __syncthreads();

    for (int c = tid; c < L_N; c += 256) {
        unsigned u = __float_as_uint(p[c]);
        unsigned key = (u & 0x80000000u) ? ~u : (u | 0x80000000u);
        atomicAdd(&hist[key >> 20], 1u);
    }
    __syncthreads();

    {
        unsigned s = 0;
#pragma unroll
        for (int b = 0; b < 16; b++) s += hist[tid * 16 + b];
        chunksum[tid] = s;
    }
    __syncthreads();

    if (tid == 0) {
        unsigned acc = 0; int bstar = 0; unsigned cgt = 0;
        for (int ch = 255; ch >= 0; ch--) {
            if (acc + chunksum[ch] >= (unsigned)TKE) {
                for (int b = ch * 16 + 15; b >= ch * 16; b--) {
                    if (acc + hist[b] >= (unsigned)TKE) { bstar = b; cgt = acc; goto found; }
                    acc += hist[b];
                }
            }
            acc += chunksum[ch];
        }
found:
        sh_bstar = bstar; sh_cgt = (int)cgt;
    }
    __syncthreads();

    int bstar = sh_bstar;
    for (int c = tid; c < L_N; c += 256) {
        float v = p[c];
        unsigned u = __float_as_uint(v);
        unsigned key = (u & 0x80000000u) ? ~u : (u | 0x80000000u);
        int bin = (int)(key >> 20);
        if (bin > bstar) {
            unsigned pos = atomicAdd(&n_sure, 1u);
            selv[pos] = v; seli[pos] = c;
        } else if (bin == bstar) {
            unsigned pos = atomicAdd(&n_cand, 1u);
            if (pos < 1024) { candv[pos] = v; candi[pos] = c; }
        }
    }
    __syncthreads();

    int m = min((int)n_cand, 1024);
    int npow = 2; while (npow < m) npow <<= 1;
    for (int i = m + tid; i < npow; i += 256) { candv[i] = -FLT_MAX; candi[i] = 0x7fffffff; }
    __syncthreads();

    bitonic_desc(candv, candi, npow, tid);

    int cgt = sh_cgt;
    int r = TKE - cgt;
    for (int i = tid; i < r; i += 256) { selv[cgt + i] = candv[i]; seli[cgt + i] = candi[i]; }
    for (int i = TKE + tid; i < 256; i += 256) { selv[i] = -FLT_MAX; seli[i] = 0x7fffffff; }
    __syncthreads();

    // ---- exact fp32 recompute of ALL TKE candidates (warp-per-candidate) ----
    for (int e = wid; e < TKE; e += 8) {
        int col = seli[e];
        const float* wr = Wenc + (size_t)col * D_N;
        float acc = 0.f;
#pragma unroll 4
        for (int d = lid; d < D_N; d += 32) acc = fmaf(xrow[d], wr[d], acc);
#pragma unroll
        for (int off = 16; off > 0; off >>= 1)
            acc += __shfl_xor_sync(0xffffffffu, acc, off);
        if (lid == 0) selv[e] = acc + benc[col];
    }
    __syncthreads();

    bitonic_desc(selv, seli, 256, tid);      // final exact ordering

    if (tid < TK2) {
        g_topv[row * TK2 + tid] = selv[tid];
        g_topi[row * TK2 + tid] = seli[tid];
    }
}

// ---------------- column stats of x for total_variance --------------------------
__global__ __launch_bounds__(256)
void colstats_kernel(const float* __restrict__ x)
{
    int col = blockIdx.x * 256 + threadIdx.x;
    int rc  = blockIdx.y;
    float s = 0.f, q = 0.f;
    for (int rr = 0; rr < 256; rr++) {
        float v = x[(size_t)(rc * 256 + rr) * D_N + col];
        s += v; q = fmaf(v, v, q);
    }
    g_colsum[rc * D_N + col] = s;
    g_colsq [rc * D_N + col] = q;
}

// ---------------- block-reduce helpers ------------------------------------------
__device__ __forceinline__ float block_reduce_f(float v, float* red, int tid)
{
    red[tid] = v; __syncthreads();
#pragma unroll
    for (int off = 128; off > 0; off >>= 1) {
        if (tid < off) red[tid] += red[tid + off];
        __syncthreads();
    }
    float r = red[0]; __syncthreads();
    return r;
}

__device__ __forceinline__ double block_reduce_d(double v, double* red, int tid)
{
    red[tid] = v; __syncthreads();
#pragma unroll
    for (int off = 128; off > 0; off >>= 1) {
        if (tid < off) red[tid] += red[tid + off];
        __syncthreads();
    }
    double r = red[0]; __syncthreads();
    return r;
}

// ---------------- fused sparse decode + per-row reductions ----------------------
__global__ __launch_bounds__(256)
void decode_kernel(const float* __restrict__ mlp, const float* __restrict__ Wdec)
{
    __shared__ float sv[TK2];
    __shared__ int   si[TK2];
    __shared__ float red[256];

    int row = blockIdx.x;
    int tid = threadIdx.x;

    if (tid < TK2) {
        float v = g_topv[row * TK2 + tid];
        sv[tid] = v > 0.f ? v : 0.f;
        si[tid] = g_topi[row * TK2 + tid];
    }
    __syncthreads();

    int c0 = tid, c1 = tid + 256, c2 = tid + 512;
    size_t base = (size_t)row * D_N;
    float sk0 = g_skip[base + c0], sk1 = g_skip[base + c1], sk2 = g_skip[base + c2];
    float R0 = mlp[base + c0] - sk0;
    float R1 = mlp[base + c1] - sk1;
    float R2 = mlp[base + c2] - sk2;

    float p0 = 0.f, p1 = 0.f, p2 = 0.f;
    float q0 = 0.f, q1 = 0.f, q2 = 0.f;
#pragma unroll 4
    for (int j = 0; j < TK2; j++) {
        float v = sv[j];
        const float* w = Wdec + (size_t)si[j] * D_N;
        p0 = fmaf(v, w[c0], p0);
        p1 = fmaf(v, w[c1], p1);
        p2 = fmaf(v, w[c2], p2);
        if (j == TK1 - 1) { q0 = p0; q1 = p1; q2 = p2; }
    }

    float e0 = R0 - q0, e1 = R1 - q1, e2 = R2 - q2;
    float s1v = e0 * e0 + e1 * e1 + e2 * e2;
    e0 = R0 - p0; e1 = R1 - p1; e2 = R2 - p2;
    float s2v = e0 * e0 + e1 * e1 + e2 * e2;
    float dsum = 2.f * (sk0 + sk1 + sk2) + q0 + q1 + q2 + p0 + p1 + p2;
    float ev = (tid < TK2) ? sv[tid] * ((tid < TK1) ? 2.f : 1.f) : 0.f;

    float r0 = block_reduce_f(s1v,  red, tid);
    float r1 = block_reduce_f(s2v,  red, tid);
    float r2 = block_reduce_f(dsum, red, tid);
    float r3 = block_reduce_f(ev,   red, tid);
    if (tid == 0) {
        g_rowp[row * 4 + 0] = r0;
        g_rowp[row * 4 + 1] = r1;
        g_rowp[row * 4 + 2] = r2;
        g_rowp[row * 4 + 3] = r3;
    }
}

// ---------------- final deterministic reduction ---------------------------------
__global__ __launch_bounds__(256)
void final_kernel(float* __restrict__ out)
{
    __shared__ double dred[256];
    int tid = threadIdx.x;

    double tv = 0.0;
    for (int col = tid; col < D_N; col += 256) {
        double S = 0.0, Q = 0.0;
        for (int i = 0; i < 32; i++) {
            S += (double)g_colsum[i * D_N + col];
            Q += (double)g_colsq [i * D_N + col];
        }
        tv += Q - S * S / (double)B_N;
    }

    double S1 = 0.0, S2 = 0.0, SD = 0.0, SE = 0.0;
    for (int r = tid; r < B_N; r += 256) {
        S1 += (double)g_rowp[r * 4 + 0];
        S2 += (double)g_rowp[r * 4 + 1];
        SD += (double)g_rowp[r * 4 + 2];
        SE += (double)g_rowp[r * 4 + 3];
    }

    tv = block_reduce_d(tv, dred, tid);
    S1 = block_reduce_d(S1, dred, tid);
    S2 = block_reduce_d(S2, dred, tid);
    SD = block_reduce_d(SD, dred, tid);
    SE = block_reduce_d(SE, dred, tid);

    if (tid == 0) {
        out[0] = (float)(SE / ((double)B_N * (double)L_N));
        out[1] = (float)(SD / ((double)B_N * (double)D_N));
        out[2] = (float)(S1 / tv + (S2 / tv) / 8.0);
    }
}

// ---------------- launch --------------------------------------------------------
extern "C" void kernel_launch(void* const* d_in, const int* in_sizes, int n_in,
                              void* d_out, int out_size)
{
    const float* x     = (const float*)d_in[0];
    const float* mlp   = (const float*)d_in[1];
    const float* Wenc  = (const float*)d_in[2];
    const float* benc  = (const float*)d_in[3];
    const float* Wdec  = (const float*)d_in[4];
    const float* bdec  = (const float*)d_in[5];
    const float* Wskip = (const float*)d_in[6];
    float* out = (float*)d_out;

    float* pre_ptr  = nullptr;
    float* skip_ptr = nullptr;
    __nv_bfloat16 *xs_ptr = nullptr, *xh_ptr = nullptr, *we_ptr = nullptr, *ws_ptr = nullptr;
    cudaGetSymbolAddress((void**)&pre_ptr,  g_pre);
    cudaGetSymbolAddress((void**)&skip_ptr, g_skip);
    cudaGetSymbolAddress((void**)&xs_ptr,   g_xs);
    cudaGetSymbolAddress((void**)&xh_ptr,   g_xh);
    cudaGetSymbolAddress((void**)&we_ptr,   g_weh);
    cudaGetSymbolAddress((void**)&ws_ptr,   g_wsT);

    cudaFuncSetAttribute(gemm_mma, cudaFuncAttributeMaxDynamicSharedMemorySize,
                         (int)GSM_TOTAL);

    // conversions
    split_x_kernel <<<(B_N * D_N) / 256, 256>>>(x);
    conv_we_kernel <<<(L_N * D_N) / 256, 256>>>(Wenc);
    split_ws_kernel<<<(D_N * D_N) / 256, 256>>>(Wskip);

    // independent column stats for total_variance
    colstats_kernel<<<dim3(3, 32), 256>>>(x);

    // skip = x @ W_skip + b_dec   via bf16x3 (K=2304, value-accurate)
    gemm_mma<<<dim3(D_N / BN, B_N / BM), 256, GSM_TOTAL>>>(xs_ptr, ws_ptr, bdec,
                                                           skip_ptr, D_N, KSPL);
    // pre scores = xh @ Wenc_h^T + b_enc   plain bf16 (K=768, selection only)
    gemm_mma<<<dim3(L_N / BN, B_N / BM), 256, GSM_TOTAL>>>(xh_ptr, we_ptr, benc,
                                                           pre_ptr, L_N, D_N);
    // per-row approx top-160 -> exact fp32 recompute -> exact top-128
    topk_kernel<<<B_N, 256>>>(x, Wenc, benc);

    // fused sparse decode + per-row loss/mean partials
    decode_kernel<<<B_N, 256>>>(mlp, Wdec);

    // final reduction to the 3 scalars
    final_kernel<<<1, 256>>>(out);
}